// round 4
// baseline (speedup 1.0000x reference)
#include <cuda_runtime.h>
#include <cstdint>
#include <math.h>

// Problem constants
constexpr int B_  = 8;
constexpr int C_  = 256;
constexpr int H_  = 31;
constexpr int W_  = 31;
constexpr int T_  = 7;
constexpr int K_  = 49;      // T*T
constexpr int OC_ = 147;     // 3*K
constexpr int NP_ = 74;      // oc pairs (padded 148)
constexpr int OH_ = 25;
constexpr int OW_ = 25;
constexpr int HW_ = H_ * W_; // 961
constexpr int OHW_= OH_ * OW_; // 625
constexpr int CT_ = 4;       // C split tiles
constexpr int CPT_= C_ / CT_;// 64 channels per tile
constexpr int YT_ = 13;      // y tiles of 2 rows
constexpr int NCHUNK_ = CPT_ / 4;  // 16 chunks of 4 channels

// Scratch (device globals; no allocations allowed)
__device__ float g_srT[B_ * HW_ * C_];                 // (B,H,W,C)
__device__ float g_tmplT[B_ * K_ * C_];                // (B,K,C)
__device__ float g_part[CT_ * B_ * OC_ * OHW_];        // conv partials
__device__ float2 g_wpk[C_ * NP_ * 9];                 // packed weights [c][pair][tap]

// packed f32x2 helpers
#define FMA_F32X2(d, a, b, c) \
    asm("fma.rn.f32x2 %0, %1, %2, %3;" : "=l"(d) : "l"(a), "l"(b), "l"(c))
#define PACK_DUP(d, v) \
    asm("mov.b64 %0, {%1, %1};" : "=l"(d) : "f"(v))
#define UNPACK2(lo, hi, p) \
    asm("mov.b64 {%0, %1}, %2;" : "=f"(lo), "=f"(hi) : "l"(p))

// cp.async helpers
#define CP_ASYNC16(dst, src) \
    asm volatile("cp.async.cg.shared.global [%0], [%1], 16;\n" :: "r"(dst), "l"(src))
#define CP_ASYNC4(dst, src, n) \
    asm volatile("cp.async.ca.shared.global [%0], [%1], 4, %2;\n" :: "r"(dst), "l"(src), "r"(n))
#define CP_COMMIT() asm volatile("cp.async.commit_group;\n" ::)
#define CP_WAIT1()  asm volatile("cp.async.wait_group 1;\n" ::)
#define CP_WAIT0()  asm volatile("cp.async.wait_group 0;\n" ::)

// ---------------------------------------------------------------------------
// transpose sr (B,C,HW) -> (B,HW,C)
// ---------------------------------------------------------------------------
__global__ void transpose_sr_kernel(const float* __restrict__ sr) {
    __shared__ float tile[32][33];
    int b  = blockIdx.z;
    int p0 = blockIdx.x * 32;
    int c0 = blockIdx.y * 32;
    int tx = threadIdx.x, ty = threadIdx.y;
    #pragma unroll
    for (int yy = 0; yy < 32; yy += 8) {
        int c = c0 + ty + yy, p = p0 + tx;
        if (p < HW_) tile[ty + yy][tx] = sr[(b * C_ + c) * HW_ + p];
    }
    __syncthreads();
    #pragma unroll
    for (int yy = 0; yy < 32; yy += 8) {
        int p = p0 + ty + yy, c = c0 + tx;
        if (p < HW_) g_srT[(b * HW_ + p) * C_ + c] = tile[tx][ty + yy];
    }
}

// transpose tmpl (B,C,K) -> (B,K,C)
__global__ void transpose_tmpl_kernel(const float* __restrict__ tmpl) {
    int t = blockIdx.x * 256 + threadIdx.x;
    if (t < B_ * K_ * C_) {
        int c = t % C_;
        int k = (t / C_) % K_;
        int b = t / (C_ * K_);
        g_tmplT[t] = tmpl[(b * C_ + c) * K_ + k];
    }
}

// pack conv weights: (147,256,3,3) -> g_wpk[c][pair][tap] float2 (oc even/odd)
__global__ void pack_weights_kernel(const float* __restrict__ w) {
    int t = blockIdx.x * 256 + threadIdx.x;
    if (t < C_ * NP_ * 9) {
        int tap = t % 9;
        int p   = (t / 9) % NP_;
        int c   = t / (9 * NP_);
        int o0 = 2 * p, o1 = 2 * p + 1;
        float v0 = w[o0 * (C_ * 9) + c * 9 + tap];
        float v1 = (o1 < OC_) ? w[o1 * (C_ * 9) + c * 9 + tap] : 0.0f;
        g_wpk[t] = make_float2(v0, v1);
    }
}

// ---------------------------------------------------------------------------
// K2: 3x3 conv on cropped region, f32x2 packed math, split-C partials,
//     cp.async double-buffered staging.
// grid = (YT_=13, B_=8, CT_=4) = 416 blocks (single wave @ 3 blocks/SM),
// block = 192. Active threads: tid<185 -> og=tid/5 (0..36, 2 oc-pairs each),
// xg=tid%5 (5 x positions each). 2 output rows per block.
// ---------------------------------------------------------------------------
__global__ void __launch_bounds__(192, 3) conv_om_kernel(
    const float* __restrict__ sr)
{
    __shared__ __align__(16) float2 s_wp[2][4 * NP_ * 9];  // 42.6 KB
    __shared__ float s_sr[2][4][4][33];                    // 16.9 KB

    const int by = blockIdx.x;
    const int b  = blockIdx.y;
    const int ct = blockIdx.z;
    const int tid = threadIdx.x;

    const int og = tid / 5;
    const int xg = tid % 5;
    const bool active = (tid < 185);
    const int x_base = xg * 5;
    const int y_base = by * 2;
    const int cbase  = ct * CPT_;

    // ---- staging (all 192 threads) ----
    auto stage = [&](int chunk, int bufi) {
        const int c0 = cbase + chunk * 4;
        // weights: 4*NP_*9 float2 = 1332 float4, contiguous
        {
            const float4* src = (const float4*)(&g_wpk[c0 * NP_ * 9]);
            unsigned int dst0 = (unsigned int)__cvta_generic_to_shared(&s_wp[bufi][0]);
            #pragma unroll
            for (int e = tid; e < (4 * NP_ * 9) / 2; e += 192)
                CP_ASYNC16(dst0 + e * 16, src + e);
        }
        // sr: 4 ch x 4 rows x 33 padded cols (zero-fill OOB via src-size=0)
        for (int e = tid; e < 4 * 4 * 33; e += 192) {
            int cc  = e / 132;
            int rem = e % 132;
            int r   = rem / 33;
            int xp  = rem % 33;
            int gy  = y_base + r - 1;
            int gx  = xp - 1;
            bool ok = (gy >= 0 && gy < H_ && gx >= 0 && gx < W_);
            const float* src = ok ? &sr[((b * C_ + c0 + cc) * H_ + gy) * W_ + gx] : sr;
            unsigned int dst = (unsigned int)__cvta_generic_to_shared(&s_sr[bufi][cc][r][xp]);
            CP_ASYNC4(dst, src, ok ? 4u : 0u);
        }
        CP_COMMIT();
    };

    unsigned long long acc[2][2][5];
    #pragma unroll
    for (int pp = 0; pp < 2; pp++)
        #pragma unroll
        for (int yy = 0; yy < 2; yy++)
            #pragma unroll
            for (int xx = 0; xx < 5; xx++) acc[pp][yy][xx] = 0ull;

    stage(0, 0);

    for (int chunk = 0; chunk < NCHUNK_; chunk++) {
        const int bufi = chunk & 1;
        if (chunk + 1 < NCHUNK_) {
            stage(chunk + 1, bufi ^ 1);
            CP_WAIT1();
        } else {
            CP_WAIT0();
        }
        __syncthreads();

        if (active) {
            #pragma unroll
            for (int cc = 0; cc < 4; cc++) {
                unsigned long long wq[2][9];
                #pragma unroll
                for (int pp = 0; pp < 2; pp++) {
                    const unsigned long long* wp =
                        (const unsigned long long*)&s_wp[bufi][(cc * NP_ + og * 2 + pp) * 9];
                    #pragma unroll
                    for (int t = 0; t < 9; t++) wq[pp][t] = wp[t];
                }
                #pragma unroll
                for (int ir = 0; ir < 4; ir++) {
                    unsigned long long rp[7];
                    #pragma unroll
                    for (int u = 0; u < 7; u++) {
                        float v = s_sr[bufi][cc][ir][x_base + u];
                        PACK_DUP(rp[u], v);
                    }
                    #pragma unroll
                    for (int dy = 0; dy < 3; dy++) {
                        int yy = ir - dy;
                        if (yy >= 0 && yy < 2) {
                            #pragma unroll
                            for (int pp = 0; pp < 2; pp++)
                                #pragma unroll
                                for (int dx = 0; dx < 3; dx++)
                                    #pragma unroll
                                    for (int xx = 0; xx < 5; xx++)
                                        FMA_F32X2(acc[pp][yy][xx],
                                                  rp[xx + dx],
                                                  wq[pp][dy * 3 + dx],
                                                  acc[pp][yy][xx]);
                        }
                    }
                }
            }
        }
        __syncthreads();   // compute done before next stage overwrites bufi
    }

    if (active) {
        #pragma unroll
        for (int pp = 0; pp < 2; pp++) {
            int o_even = og * 4 + pp * 2;
            #pragma unroll
            for (int yy = 0; yy < 2; yy++) {
                int y = y_base + yy;
                if (y >= OH_) continue;
                #pragma unroll
                for (int xx = 0; xx < 5; xx++) {
                    float lo, hi;
                    UNPACK2(lo, hi, acc[pp][yy][xx]);
                    int base = ct * (B_ * OC_ * OHW_) +
                               (b * OC_ + o_even) * OHW_ + y * OW_ + x_base + xx;
                    g_part[base] = lo;
                    if (o_even + 1 < OC_) g_part[base + OHW_] = hi;
                }
            }
        }
    }
}

// ---------------------------------------------------------------------------
// K3: deformable bilinear gather + weighted correlation (vectorized).
// Metadata phase also sums the CT_ conv partials + bias (reduce fused here).
// grid = 1250 blocks, block = 256 = 4 groups x 64 threads (float4 channels).
// ---------------------------------------------------------------------------
__global__ void __launch_bounds__(256) deform_xcorr_kernel(
    float* __restrict__ out, const float* __restrict__ bias)
{
    __shared__ int4   sA4[4][K_];
    __shared__ float4 sW4[4][K_];

    const int tid = threadIdx.x;

    if (tid < 4 * K_) {
        const int g2 = tid / K_;
        const int k  = tid % K_;
        const int p  = blockIdx.x * 4 + g2;
        const int b  = p / OHW_;
        const int rem = p % OHW_;
        const int i  = rem / OW_;
        const int j  = rem % OW_;

        const int pos = i * OW_ + j;
        const int base = (b * OC_ + k) * OHW_ + pos;
        float oy = bias[k];
        float ox = bias[k + 49];
        float mz = bias[k + 98];
        #pragma unroll
        for (int ct = 0; ct < CT_; ct++) {
            const float* pp = g_part + ct * (B_ * OC_ * OHW_);
            oy += pp[base];
            ox += pp[base + 49 * OHW_];
            mz += pp[base + 98 * OHW_];
        }
        float m = 1.0f / (1.0f + __expf(-mz));

        float ys = (float)i + (float)(k / T_) + oy;
        float xs = (float)j + (float)(k % T_) + ox;
        float y0f = floorf(ys), x0f = floorf(xs);
        float wy = ys - y0f, wx = xs - x0f;
        float y1f = y0f + 1.0f, x1f = x0f + 1.0f;

        bool vy0 = (y0f >= 0.0f) && (y0f <= (float)(H_ - 1));
        bool vy1 = (y1f >= 0.0f) && (y1f <= (float)(H_ - 1));
        bool vx0 = (x0f >= 0.0f) && (x0f <= (float)(W_ - 1));
        bool vx1 = (x1f >= 0.0f) && (x1f <= (float)(W_ - 1));

        float w00 = (1.0f - wy) * (1.0f - wx) * m; if (!(vy0 && vx0)) w00 = 0.0f;
        float w01 = (1.0f - wy) * wx          * m; if (!(vy0 && vx1)) w01 = 0.0f;
        float w10 = wy          * (1.0f - wx) * m; if (!(vy1 && vx0)) w10 = 0.0f;
        float w11 = wy          * wx          * m; if (!(vy1 && vx1)) w11 = 0.0f;

        int y0 = (int)fminf(fmaxf(y0f, 0.0f), (float)(H_ - 1));
        int y1 = (int)fminf(fmaxf(y1f, 0.0f), (float)(H_ - 1));
        int x0 = (int)fminf(fmaxf(x0f, 0.0f), (float)(W_ - 1));
        int x1 = (int)fminf(fmaxf(x1f, 0.0f), (float)(W_ - 1));

        sA4[g2][k] = make_int4((y0 * W_ + x0) * (C_ * 4),
                               (y0 * W_ + x1) * (C_ * 4),
                               (y1 * W_ + x0) * (C_ * 4),
                               (y1 * W_ + x1) * (C_ * 4));
        sW4[g2][k] = make_float4(w00, w01, w10, w11);
    }
    __syncthreads();

    const int g  = tid / 64;
    const int c4 = tid % 64;
    const int p  = blockIdx.x * 4 + g;
    const int b  = p / OHW_;
    const int rem = p % OHW_;
    const int i  = rem / OW_;
    const int j  = rem % OW_;

    const char* srTb = (const char*)(g_srT + (size_t)b * HW_ * C_) + c4 * 16;
    const float4* tT = (const float4*)(g_tmplT + (size_t)b * K_ * C_) + c4;

    float4 acc = make_float4(0.f, 0.f, 0.f, 0.f);
    #pragma unroll 7
    for (int k = 0; k < K_; k++) {
        int4   a  = sA4[g][k];
        float4 wv = sW4[g][k];
        float4 v00 = *(const float4*)(srTb + a.x);
        float4 v01 = *(const float4*)(srTb + a.y);
        float4 v10 = *(const float4*)(srTb + a.z);
        float4 v11 = *(const float4*)(srTb + a.w);
        float4 tv  = tT[(size_t)k * 64];

        float sx, sy, sz, sw;
        sx = wv.x * v00.x; sx = fmaf(wv.y, v01.x, sx); sx = fmaf(wv.z, v10.x, sx); sx = fmaf(wv.w, v11.x, sx);
        sy = wv.x * v00.y; sy = fmaf(wv.y, v01.y, sy); sy = fmaf(wv.z, v10.y, sy); sy = fmaf(wv.w, v11.y, sy);
        sz = wv.x * v00.z; sz = fmaf(wv.y, v01.z, sz); sz = fmaf(wv.z, v10.z, sz); sz = fmaf(wv.w, v11.z, sz);
        sw = wv.x * v00.w; sw = fmaf(wv.y, v01.w, sw); sw = fmaf(wv.z, v10.w, sw); sw = fmaf(wv.w, v11.w, sw);

        acc.x = fmaf(tv.x, sx, acc.x);
        acc.y = fmaf(tv.y, sy, acc.y);
        acc.z = fmaf(tv.z, sz, acc.z);
        acc.w = fmaf(tv.w, sw, acc.w);
    }

    const int c = c4 * 4;
    float* op = out + ((size_t)(b * C_ + c) * OH_ + i) * OW_ + j;
    op[0]        = acc.x;
    op[OHW_]     = acc.y;
    op[2 * OHW_] = acc.z;
    op[3 * OHW_] = acc.w;
}

// ---------------------------------------------------------------------------
extern "C" void kernel_launch(void* const* d_in, const int* in_sizes, int n_in,
                              void* d_out, int out_size)
{
    const float* sr   = (const float*)d_in[0];
    const float* tmpl = (const float*)d_in[1];
    const float* w    = (const float*)d_in[2];
    const float* bias = (const float*)d_in[3];
    float* out = (float*)d_out;

    {
        dim3 tb(32, 8);
        dim3 tg((HW_ + 31) / 32, C_ / 32, B_);
        transpose_sr_kernel<<<tg, tb>>>(sr);
    }
    {
        int n = B_ * K_ * C_;
        transpose_tmpl_kernel<<<(n + 255) / 256, 256>>>(tmpl);
    }
    {
        int n = C_ * NP_ * 9;
        pack_weights_kernel<<<(n + 255) / 256, 256>>>(w);
    }
    {
        dim3 g(YT_, B_, CT_);
        conv_om_kernel<<<g, 192>>>(sr);
    }
    {
        deform_xcorr_kernel<<<1250, 256>>>(out, bias);
    }
}

// round 5
// speedup vs baseline: 1.4476x; 1.4476x over previous
#include <cuda_runtime.h>
#include <cstdint>
#include <math.h>

// Problem constants
constexpr int B_  = 8;
constexpr int C_  = 256;
constexpr int H_  = 31;
constexpr int W_  = 31;
constexpr int T_  = 7;
constexpr int K_  = 49;      // T*T
constexpr int OC_ = 147;     // 3*K
constexpr int NP_ = 74;      // oc pairs (padded 148)
constexpr int OH_ = 25;
constexpr int OW_ = 25;
constexpr int HW_ = H_ * W_; // 961
constexpr int OHW_= OH_ * OW_; // 625
constexpr int CT_ = 4;       // C split tiles
constexpr int CPT_= C_ / CT_;// 64 channels per tile
constexpr int YT_ = 13;      // y tiles of 2 rows
constexpr int NCHUNK_ = CPT_ / 4;  // 16 chunks of 4 channels

// Scratch (device globals; no allocations allowed)
__device__ float g_srT[B_ * HW_ * C_];                 // (B,H,W,C)
__device__ float g_tmplT[B_ * K_ * C_];                // (B,K,C)
__device__ float g_om[B_ * OC_ * OHW_];                // reduced conv out
__device__ float g_part[CT_ * B_ * OC_ * OHW_];        // conv partials
__device__ float2 g_wpk[C_ * NP_ * 9];                 // packed weights [c][pair][tap]

// packed f32x2 helpers
#define FMA_F32X2(d, a, b, c) \
    asm("fma.rn.f32x2 %0, %1, %2, %3;" : "=l"(d) : "l"(a), "l"(b), "l"(c))
#define PACK_DUP(d, v) \
    asm("mov.b64 %0, {%1, %1};" : "=l"(d) : "f"(v))
#define UNPACK2(lo, hi, p) \
    asm("mov.b64 {%0, %1}, %2;" : "=f"(lo), "=f"(hi) : "l"(p))

// ---------------------------------------------------------------------------
// transpose sr (B,C,HW) -> (B,HW,C)
// ---------------------------------------------------------------------------
__global__ void transpose_sr_kernel(const float* __restrict__ sr) {
    __shared__ float tile[32][33];
    int b  = blockIdx.z;
    int p0 = blockIdx.x * 32;
    int c0 = blockIdx.y * 32;
    int tx = threadIdx.x, ty = threadIdx.y;
    #pragma unroll
    for (int yy = 0; yy < 32; yy += 8) {
        int c = c0 + ty + yy, p = p0 + tx;
        if (p < HW_) tile[ty + yy][tx] = sr[(b * C_ + c) * HW_ + p];
    }
    __syncthreads();
    #pragma unroll
    for (int yy = 0; yy < 32; yy += 8) {
        int p = p0 + ty + yy, c = c0 + tx;
        if (p < HW_) g_srT[(b * HW_ + p) * C_ + c] = tile[tx][ty + yy];
    }
}

// transpose tmpl (B,C,K) -> (B,K,C)
__global__ void transpose_tmpl_kernel(const float* __restrict__ tmpl) {
    int t = blockIdx.x * 256 + threadIdx.x;
    if (t < B_ * K_ * C_) {
        int c = t % C_;
        int k = (t / C_) % K_;
        int b = t / (C_ * K_);
        g_tmplT[t] = tmpl[(b * C_ + c) * K_ + k];
    }
}

// pack conv weights: (147,256,3,3) -> g_wpk[c][pair][tap] float2 (oc even/odd)
__global__ void pack_weights_kernel(const float* __restrict__ w) {
    int t = blockIdx.x * 256 + threadIdx.x;
    if (t < C_ * NP_ * 9) {
        int tap = t % 9;
        int p   = (t / 9) % NP_;
        int c   = t / (9 * NP_);
        int o0 = 2 * p, o1 = 2 * p + 1;
        float v0 = w[o0 * (C_ * 9) + c * 9 + tap];
        float v1 = (o1 < OC_) ? w[o1 * (C_ * 9) + c * 9 + tap] : 0.0f;
        g_wpk[t] = make_float2(v0, v1);
    }
}

// ---------------------------------------------------------------------------
// K2: 3x3 conv on cropped region, f32x2 packed math, split-C partials.
// grid = (YT_=13, B_=8, CT_=4) = 416 blocks, block = 384 threads (12 warps),
// smem 23.4KB -> 2 blocks/SM = 24 warps.
// Thread (tid<370): og = tid/5 (0..73) -> ONE oc pair; xg = tid%5 -> 5 x.
// 2 output rows per block; C reduced in 16 chunks of 4 channels.
// ---------------------------------------------------------------------------
__global__ void __launch_bounds__(384, 2) conv_om_kernel(
    const float* __restrict__ sr)
{
    __shared__ __align__(16) float2 s_wp[4 * NP_ * 9];  // 21.3 KB
    __shared__ float s_sr[4][4][33];                    // 2.1 KB

    const int by = blockIdx.x;
    const int b  = blockIdx.y;
    const int ct = blockIdx.z;
    const int tid = threadIdx.x;

    const int og = tid / 5;          // 0..76
    const int xg = tid % 5;
    const bool active = (og < NP_);  // 370 active
    const int x_base = xg * 5;
    const int y_base = by * 2;
    const int cbase  = ct * CPT_;

    unsigned long long acc[2][5];    // [yy][xx]
    #pragma unroll
    for (int yy = 0; yy < 2; yy++)
        #pragma unroll
        for (int xx = 0; xx < 5; xx++) acc[yy][xx] = 0ull;

    for (int chunk = 0; chunk < NCHUNK_; chunk++) {
        const int c0 = cbase + chunk * 4;
        __syncthreads();
        // stage weights: 4*NP_*9 float2 = 1332 float4, contiguous
        {
            const float4* src = (const float4*)(&g_wpk[c0 * NP_ * 9]);
            float4* dst = (float4*)s_wp;
            for (int e = tid; e < (4 * NP_ * 9) / 2; e += 384)
                dst[e] = src[e];
        }
        // stage sr: 4 ch x rows y_base-1..y_base+2 x padded cols -1..31
        for (int e = tid; e < 4 * 4 * 33; e += 384) {
            int cc  = e / 132;
            int rem = e % 132;
            int r   = rem / 33;
            int xp  = rem % 33;
            int gy  = y_base + r - 1;
            int gx  = xp - 1;
            float v = 0.f;
            if (gy >= 0 && gy < H_ && gx >= 0 && gx < W_)
                v = sr[((b * C_ + c0 + cc) * H_ + gy) * W_ + gx];
            s_sr[cc][r][xp] = v;
        }
        __syncthreads();

        if (active) {
            #pragma unroll
            for (int cc = 0; cc < 4; cc++) {
                unsigned long long wq[9];
                {
                    const unsigned long long* wp =
                        (const unsigned long long*)&s_wp[(cc * NP_ + og) * 9];
                    #pragma unroll
                    for (int t = 0; t < 9; t++) wq[t] = wp[t];
                }
                #pragma unroll
                for (int ir = 0; ir < 4; ir++) {
                    unsigned long long rp[7];
                    #pragma unroll
                    for (int u = 0; u < 7; u++) {
                        float v = s_sr[cc][ir][x_base + u];
                        PACK_DUP(rp[u], v);
                    }
                    #pragma unroll
                    for (int dy = 0; dy < 3; dy++) {
                        int yy = ir - dy;
                        if (yy >= 0 && yy < 2) {
                            #pragma unroll
                            for (int dx = 0; dx < 3; dx++)
                                #pragma unroll
                                for (int xx = 0; xx < 5; xx++)
                                    FMA_F32X2(acc[yy][xx],
                                              rp[xx + dx],
                                              wq[dy * 3 + dx],
                                              acc[yy][xx]);
                        }
                    }
                }
            }
        }
    }

    if (active) {
        int o_even = og * 2;
        #pragma unroll
        for (int yy = 0; yy < 2; yy++) {
            int y = y_base + yy;
            if (y >= OH_) continue;
            #pragma unroll
            for (int xx = 0; xx < 5; xx++) {
                float lo, hi;
                UNPACK2(lo, hi, acc[yy][xx]);
                int base = ct * (B_ * OC_ * OHW_) +
                           (b * OC_ + o_even) * OHW_ + y * OW_ + x_base + xx;
                g_part[base] = lo;
                if (o_even + 1 < OC_) g_part[base + OHW_] = hi;
            }
        }
    }
}

// sum partials + bias -> g_om
__global__ void reduce_om_kernel(const float* __restrict__ bias) {
    int t = blockIdx.x * 256 + threadIdx.x;
    if (t < B_ * OC_ * OHW_) {
        int oc = (t / OHW_) % OC_;
        float s = bias[oc];
        #pragma unroll
        for (int ct = 0; ct < CT_; ct++)
            s += g_part[ct * (B_ * OC_ * OHW_) + t];
        g_om[t] = s;
    }
}

// ---------------------------------------------------------------------------
// K3: deformable bilinear gather + weighted correlation (vectorized).
// grid = 1250 blocks, block = 256 = 4 groups x 64 threads (float4 channels).
// ---------------------------------------------------------------------------
__global__ void __launch_bounds__(256) deform_xcorr_kernel(float* __restrict__ out)
{
    __shared__ int4   sA4[4][K_];
    __shared__ float4 sW4[4][K_];

    const int tid = threadIdx.x;

    if (tid < 4 * K_) {
        const int g2 = tid / K_;
        const int k  = tid % K_;
        const int p  = blockIdx.x * 4 + g2;
        const int b  = p / OHW_;
        const int rem = p % OHW_;
        const int i  = rem / OW_;
        const int j  = rem % OW_;

        const int base = (b * OC_ + k) * OHW_ + i * OW_ + j;
        float oy = g_om[base];
        float ox = g_om[base + 49 * OHW_];
        float mz = g_om[base + 98 * OHW_];
        float m  = 1.0f / (1.0f + __expf(-mz));

        float ys = (float)i + (float)(k / T_) + oy;
        float xs = (float)j + (float)(k % T_) + ox;
        float y0f = floorf(ys), x0f = floorf(xs);
        float wy = ys - y0f, wx = xs - x0f;
        float y1f = y0f + 1.0f, x1f = x0f + 1.0f;

        bool vy0 = (y0f >= 0.0f) && (y0f <= (float)(H_ - 1));
        bool vy1 = (y1f >= 0.0f) && (y1f <= (float)(H_ - 1));
        bool vx0 = (x0f >= 0.0f) && (x0f <= (float)(W_ - 1));
        bool vx1 = (x1f >= 0.0f) && (x1f <= (float)(W_ - 1));

        float w00 = (1.0f - wy) * (1.0f - wx) * m; if (!(vy0 && vx0)) w00 = 0.0f;
        float w01 = (1.0f - wy) * wx          * m; if (!(vy0 && vx1)) w01 = 0.0f;
        float w10 = wy          * (1.0f - wx) * m; if (!(vy1 && vx0)) w10 = 0.0f;
        float w11 = wy          * wx          * m; if (!(vy1 && vx1)) w11 = 0.0f;

        int y0 = (int)fminf(fmaxf(y0f, 0.0f), (float)(H_ - 1));
        int y1 = (int)fminf(fmaxf(y1f, 0.0f), (float)(H_ - 1));
        int x0 = (int)fminf(fmaxf(x0f, 0.0f), (float)(W_ - 1));
        int x1 = (int)fminf(fmaxf(x1f, 0.0f), (float)(W_ - 1));

        sA4[g2][k] = make_int4((y0 * W_ + x0) * (C_ * 4),
                               (y0 * W_ + x1) * (C_ * 4),
                               (y1 * W_ + x0) * (C_ * 4),
                               (y1 * W_ + x1) * (C_ * 4));
        sW4[g2][k] = make_float4(w00, w01, w10, w11);
    }
    __syncthreads();

    const int g  = tid / 64;
    const int c4 = tid % 64;
    const int p  = blockIdx.x * 4 + g;
    const int b  = p / OHW_;
    const int rem = p % OHW_;
    const int i  = rem / OW_;
    const int j  = rem % OW_;

    const char* srTb = (const char*)(g_srT + (size_t)b * HW_ * C_) + c4 * 16;
    const float4* tT = (const float4*)(g_tmplT + (size_t)b * K_ * C_) + c4;

    float4 acc = make_float4(0.f, 0.f, 0.f, 0.f);
    #pragma unroll 7
    for (int k = 0; k < K_; k++) {
        int4   a  = sA4[g][k];
        float4 wv = sW4[g][k];
        float4 v00 = *(const float4*)(srTb + a.x);
        float4 v01 = *(const float4*)(srTb + a.y);
        float4 v10 = *(const float4*)(srTb + a.z);
        float4 v11 = *(const float4*)(srTb + a.w);
        float4 tv  = tT[(size_t)k * 64];

        float sx, sy, sz, sw;
        sx = wv.x * v00.x; sx = fmaf(wv.y, v01.x, sx); sx = fmaf(wv.z, v10.x, sx); sx = fmaf(wv.w, v11.x, sx);
        sy = wv.x * v00.y; sy = fmaf(wv.y, v01.y, sy); sy = fmaf(wv.z, v10.y, sy); sy = fmaf(wv.w, v11.y, sy);
        sz = wv.x * v00.z; sz = fmaf(wv.y, v01.z, sz); sz = fmaf(wv.z, v10.z, sz); sz = fmaf(wv.w, v11.z, sz);
        sw = wv.x * v00.w; sw = fmaf(wv.y, v01.w, sw); sw = fmaf(wv.z, v10.w, sw); sw = fmaf(wv.w, v11.w, sw);

        acc.x = fmaf(tv.x, sx, acc.x);
        acc.y = fmaf(tv.y, sy, acc.y);
        acc.z = fmaf(tv.z, sz, acc.z);
        acc.w = fmaf(tv.w, sw, acc.w);
    }

    const int c = c4 * 4;
    float* op = out + ((size_t)(b * C_ + c) * OH_ + i) * OW_ + j;
    op[0]        = acc.x;
    op[OHW_]     = acc.y;
    op[2 * OHW_] = acc.z;
    op[3 * OHW_] = acc.w;
}

// ---------------------------------------------------------------------------
extern "C" void kernel_launch(void* const* d_in, const int* in_sizes, int n_in,
                              void* d_out, int out_size)
{
    const float* sr   = (const float*)d_in[0];
    const float* tmpl = (const float*)d_in[1];
    const float* w    = (const float*)d_in[2];
    const float* bias = (const float*)d_in[3];
    float* out = (float*)d_out;

    {
        dim3 tb(32, 8);
        dim3 tg((HW_ + 31) / 32, C_ / 32, B_);
        transpose_sr_kernel<<<tg, tb>>>(sr);
    }
    {
        int n = B_ * K_ * C_;
        transpose_tmpl_kernel<<<(n + 255) / 256, 256>>>(tmpl);
    }
    {
        int n = C_ * NP_ * 9;
        pack_weights_kernel<<<(n + 255) / 256, 256>>>(w);
    }
    {
        dim3 g(YT_, B_, CT_);
        conv_om_kernel<<<g, 384>>>(sr);
    }
    {
        int n = B_ * OC_ * OHW_;
        reduce_om_kernel<<<(n + 255) / 256, 256>>>(bias);
    }
    {
        deform_xcorr_kernel<<<1250, 256>>>(out);
    }
}

// round 6
// speedup vs baseline: 1.5375x; 1.0621x over previous
#include <cuda_runtime.h>
#include <cstdint>
#include <math.h>

// Problem constants
constexpr int B_  = 8;
constexpr int C_  = 256;
constexpr int H_  = 31;
constexpr int W_  = 31;
constexpr int T_  = 7;
constexpr int K_  = 49;      // T*T
constexpr int OC_ = 147;     // 3*K
constexpr int NP_ = 74;      // oc pairs (padded 148)
constexpr int OH_ = 25;
constexpr int OW_ = 25;
constexpr int HW_ = H_ * W_; // 961
constexpr int OHW_= OH_ * OW_; // 625
constexpr int CT_ = 8;       // C split tiles
constexpr int CPT_= C_ / CT_;// 32 channels per tile
constexpr int YT_ = 7;       // y tiles of 4 rows
constexpr int NCHUNK_ = CPT_ / 4;  // 8 chunks of 4 channels

// Scratch (device globals; no allocations allowed)
__device__ float g_srT[B_ * HW_ * C_];                 // (B,H,W,C)
__device__ float g_tmplT[B_ * K_ * C_];                // (B,K,C)
__device__ float g_om[B_ * OC_ * OHW_];                // reduced conv out
__device__ float g_part[CT_ * B_ * OC_ * OHW_];        // conv partials
__device__ float2 g_wpk[C_ * NP_ * 9];                 // packed weights [c][pair][tap]

// packed f32x2 helpers
#define FMA_F32X2(d, a, b, c) \
    asm("fma.rn.f32x2 %0, %1, %2, %3;" : "=l"(d) : "l"(a), "l"(b), "l"(c))
#define PACK_DUP(d, v) \
    asm("mov.b64 %0, {%1, %1};" : "=l"(d) : "f"(v))
#define UNPACK2(lo, hi, p) \
    asm("mov.b64 {%0, %1}, %2;" : "=f"(lo), "=f"(hi) : "l"(p))

// ---------------------------------------------------------------------------
// transpose sr (B,C,HW) -> (B,HW,C)
// ---------------------------------------------------------------------------
__global__ void transpose_sr_kernel(const float* __restrict__ sr) {
    __shared__ float tile[32][33];
    int b  = blockIdx.z;
    int p0 = blockIdx.x * 32;
    int c0 = blockIdx.y * 32;
    int tx = threadIdx.x, ty = threadIdx.y;
    #pragma unroll
    for (int yy = 0; yy < 32; yy += 8) {
        int c = c0 + ty + yy, p = p0 + tx;
        if (p < HW_) tile[ty + yy][tx] = sr[(b * C_ + c) * HW_ + p];
    }
    __syncthreads();
    #pragma unroll
    for (int yy = 0; yy < 32; yy += 8) {
        int p = p0 + ty + yy, c = c0 + tx;
        if (p < HW_) g_srT[(b * HW_ + p) * C_ + c] = tile[tx][ty + yy];
    }
}

// transpose tmpl (B,C,K) -> (B,K,C)
__global__ void transpose_tmpl_kernel(const float* __restrict__ tmpl) {
    int t = blockIdx.x * 256 + threadIdx.x;
    if (t < B_ * K_ * C_) {
        int c = t % C_;
        int k = (t / C_) % K_;
        int b = t / (C_ * K_);
        g_tmplT[t] = tmpl[(b * C_ + c) * K_ + k];
    }
}

// pack conv weights: (147,256,3,3) -> g_wpk[c][pair][tap] float2 (oc even/odd)
__global__ void pack_weights_kernel(const float* __restrict__ w) {
    int t = blockIdx.x * 256 + threadIdx.x;
    if (t < C_ * NP_ * 9) {
        int tap = t % 9;
        int p   = (t / 9) % NP_;
        int c   = t / (9 * NP_);
        int o0 = 2 * p, o1 = 2 * p + 1;
        float v0 = w[o0 * (C_ * 9) + c * 9 + tap];
        float v1 = (o1 < OC_) ? w[o1 * (C_ * 9) + c * 9 + tap] : 0.0f;
        g_wpk[t] = make_float2(v0, v1);
    }
}

// ---------------------------------------------------------------------------
// K2: 3x3 conv on cropped region, f32x2 packed math, split-C partials.
// grid = (YT_=7, B_=8, CT_=8) = 448 blocks, block = 384 threads (12 warps),
// smem ~24.5KB -> 2 blocks/SM.
// Thread (og=tid/5 < 74): ONE oc pair, xg=tid%5 -> 5 x positions,
// FOUR output rows per block (raises FMA : smem-crossbar ratio to ~1.5).
// C reduced in 8 chunks of 4 channels.
// ---------------------------------------------------------------------------
__global__ void __launch_bounds__(384, 2) conv_om_kernel(
    const float* __restrict__ sr)
{
    __shared__ __align__(16) float2 s_wp[4 * NP_ * 9];  // 21.3 KB
    __shared__ float s_sr[4][6][33];                    // 3.1 KB

    const int by = blockIdx.x;
    const int b  = blockIdx.y;
    const int ct = blockIdx.z;
    const int tid = threadIdx.x;

    const int og = tid / 5;          // 0..76
    const int xg = tid % 5;
    const bool active = (og < NP_);  // 370 active
    const int x_base = xg * 5;
    const int y_base = by * 4;
    const int cbase  = ct * CPT_;

    unsigned long long acc[4][5];    // [yy][xx]
    #pragma unroll
    for (int yy = 0; yy < 4; yy++)
        #pragma unroll
        for (int xx = 0; xx < 5; xx++) acc[yy][xx] = 0ull;

    for (int chunk = 0; chunk < NCHUNK_; chunk++) {
        const int c0 = cbase + chunk * 4;
        __syncthreads();
        // stage weights: 4*NP_*9 float2 = 1332 float4, contiguous
        {
            const float4* src = (const float4*)(&g_wpk[c0 * NP_ * 9]);
            float4* dst = (float4*)s_wp;
            for (int e = tid; e < (4 * NP_ * 9) / 2; e += 384)
                dst[e] = src[e];
        }
        // stage sr: 4 ch x rows y_base-1..y_base+4 x padded cols -1..31
        for (int e = tid; e < 4 * 6 * 33; e += 384) {
            int cc  = e / 198;
            int rem = e % 198;
            int r   = rem / 33;
            int xp  = rem % 33;
            int gy  = y_base + r - 1;
            int gx  = xp - 1;
            float v = 0.f;
            if (gy >= 0 && gy < H_ && gx >= 0 && gx < W_)
                v = sr[((b * C_ + c0 + cc) * H_ + gy) * W_ + gx];
            s_sr[cc][r][xp] = v;
        }
        __syncthreads();

        if (active) {
            #pragma unroll
            for (int cc = 0; cc < 4; cc++) {
                unsigned long long wq[9];
                {
                    const unsigned long long* wp =
                        (const unsigned long long*)&s_wp[(cc * NP_ + og) * 9];
                    #pragma unroll
                    for (int t = 0; t < 9; t++) wq[t] = wp[t];
                }
                #pragma unroll
                for (int ir = 0; ir < 6; ir++) {
                    #pragma unroll
                    for (int u = 0; u < 7; u++) {
                        unsigned long long rp;
                        {
                            float v = s_sr[cc][ir][x_base + u];
                            PACK_DUP(rp, v);
                        }
                        #pragma unroll
                        for (int dx = 0; dx < 3; dx++) {
                            const int xx = u - dx;
                            if (xx >= 0 && xx < 5) {
                                #pragma unroll
                                for (int dy = 0; dy < 3; dy++) {
                                    const int yy = ir - dy;
                                    if (yy >= 0 && yy < 4)
                                        FMA_F32X2(acc[yy][xx], rp,
                                                  wq[dy * 3 + dx], acc[yy][xx]);
                                }
                            }
                        }
                    }
                }
            }
        }
    }

    if (active) {
        int o_even = og * 2;
        #pragma unroll
        for (int yy = 0; yy < 4; yy++) {
            int y = y_base + yy;
            if (y >= OH_) continue;
            #pragma unroll
            for (int xx = 0; xx < 5; xx++) {
                float lo, hi;
                UNPACK2(lo, hi, acc[yy][xx]);
                int base = ct * (B_ * OC_ * OHW_) +
                           (b * OC_ + o_even) * OHW_ + y * OW_ + x_base + xx;
                g_part[base] = lo;
                if (o_even + 1 < OC_) g_part[base + OHW_] = hi;
            }
        }
    }
}

// sum partials + bias -> g_om
__global__ void reduce_om_kernel(const float* __restrict__ bias) {
    int t = blockIdx.x * 256 + threadIdx.x;
    if (t < B_ * OC_ * OHW_) {
        int oc = (t / OHW_) % OC_;
        float s = bias[oc];
        #pragma unroll
        for (int ct = 0; ct < CT_; ct++)
            s += g_part[ct * (B_ * OC_ * OHW_) + t];
        g_om[t] = s;
    }
}

// ---------------------------------------------------------------------------
// K3: deformable bilinear gather + weighted correlation (vectorized).
// grid = 1250 blocks, block = 256 = 4 groups x 64 threads (float4 channels).
// ---------------------------------------------------------------------------
__global__ void __launch_bounds__(256) deform_xcorr_kernel(float* __restrict__ out)
{
    __shared__ int4   sA4[4][K_];
    __shared__ float4 sW4[4][K_];

    const int tid = threadIdx.x;

    if (tid < 4 * K_) {
        const int g2 = tid / K_;
        const int k  = tid % K_;
        const int p  = blockIdx.x * 4 + g2;
        const int b  = p / OHW_;
        const int rem = p % OHW_;
        const int i  = rem / OW_;
        const int j  = rem % OW_;

        const int base = (b * OC_ + k) * OHW_ + i * OW_ + j;
        float oy = g_om[base];
        float ox = g_om[base + 49 * OHW_];
        float mz = g_om[base + 98 * OHW_];
        float m  = 1.0f / (1.0f + __expf(-mz));

        float ys = (float)i + (float)(k / T_) + oy;
        float xs = (float)j + (float)(k % T_) + ox;
        float y0f = floorf(ys), x0f = floorf(xs);
        float wy = ys - y0f, wx = xs - x0f;
        float y1f = y0f + 1.0f, x1f = x0f + 1.0f;

        bool vy0 = (y0f >= 0.0f) && (y0f <= (float)(H_ - 1));
        bool vy1 = (y1f >= 0.0f) && (y1f <= (float)(H_ - 1));
        bool vx0 = (x0f >= 0.0f) && (x0f <= (float)(W_ - 1));
        bool vx1 = (x1f >= 0.0f) && (x1f <= (float)(W_ - 1));

        float w00 = (1.0f - wy) * (1.0f - wx) * m; if (!(vy0 && vx0)) w00 = 0.0f;
        float w01 = (1.0f - wy) * wx          * m; if (!(vy0 && vx1)) w01 = 0.0f;
        float w10 = wy          * (1.0f - wx) * m; if (!(vy1 && vx0)) w10 = 0.0f;
        float w11 = wy          * wx          * m; if (!(vy1 && vx1)) w11 = 0.0f;

        int y0 = (int)fminf(fmaxf(y0f, 0.0f), (float)(H_ - 1));
        int y1 = (int)fminf(fmaxf(y1f, 0.0f), (float)(H_ - 1));
        int x0 = (int)fminf(fmaxf(x0f, 0.0f), (float)(W_ - 1));
        int x1 = (int)fminf(fmaxf(x1f, 0.0f), (float)(W_ - 1));

        sA4[g2][k] = make_int4((y0 * W_ + x0) * (C_ * 4),
                               (y0 * W_ + x1) * (C_ * 4),
                               (y1 * W_ + x0) * (C_ * 4),
                               (y1 * W_ + x1) * (C_ * 4));
        sW4[g2][k] = make_float4(w00, w01, w10, w11);
    }
    __syncthreads();

    const int g  = tid / 64;
    const int c4 = tid % 64;
    const int p  = blockIdx.x * 4 + g;
    const int b  = p / OHW_;
    const int rem = p % OHW_;
    const int i  = rem / OW_;
    const int j  = rem % OW_;

    const char* srTb = (const char*)(g_srT + (size_t)b * HW_ * C_) + c4 * 16;
    const float4* tT = (const float4*)(g_tmplT + (size_t)b * K_ * C_) + c4;

    float4 acc = make_float4(0.f, 0.f, 0.f, 0.f);
    #pragma unroll 7
    for (int k = 0; k < K_; k++) {
        int4   a  = sA4[g][k];
        float4 wv = sW4[g][k];
        float4 v00 = *(const float4*)(srTb + a.x);
        float4 v01 = *(const float4*)(srTb + a.y);
        float4 v10 = *(const float4*)(srTb + a.z);
        float4 v11 = *(const float4*)(srTb + a.w);
        float4 tv  = tT[(size_t)k * 64];

        float sx, sy, sz, sw;
        sx = wv.x * v00.x; sx = fmaf(wv.y, v01.x, sx); sx = fmaf(wv.z, v10.x, sx); sx = fmaf(wv.w, v11.x, sx);
        sy = wv.x * v00.y; sy = fmaf(wv.y, v01.y, sy); sy = fmaf(wv.z, v10.y, sy); sy = fmaf(wv.w, v11.y, sy);
        sz = wv.x * v00.z; sz = fmaf(wv.y, v01.z, sz); sz = fmaf(wv.z, v10.z, sz); sz = fmaf(wv.w, v11.z, sz);
        sw = wv.x * v00.w; sw = fmaf(wv.y, v01.w, sw); sw = fmaf(wv.z, v10.w, sw); sw = fmaf(wv.w, v11.w, sw);

        acc.x = fmaf(tv.x, sx, acc.x);
        acc.y = fmaf(tv.y, sy, acc.y);
        acc.z = fmaf(tv.z, sz, acc.z);
        acc.w = fmaf(tv.w, sw, acc.w);
    }

    const int c = c4 * 4;
    float* op = out + ((size_t)(b * C_ + c) * OH_ + i) * OW_ + j;
    op[0]        = acc.x;
    op[OHW_]     = acc.y;
    op[2 * OHW_] = acc.z;
    op[3 * OHW_] = acc.w;
}

// ---------------------------------------------------------------------------
extern "C" void kernel_launch(void* const* d_in, const int* in_sizes, int n_in,
                              void* d_out, int out_size)
{
    const float* sr   = (const float*)d_in[0];
    const float* tmpl = (const float*)d_in[1];
    const float* w    = (const float*)d_in[2];
    const float* bias = (const float*)d_in[3];
    float* out = (float*)d_out;

    {
        dim3 tb(32, 8);
        dim3 tg((HW_ + 31) / 32, C_ / 32, B_);
        transpose_sr_kernel<<<tg, tb>>>(sr);
    }
    {
        int n = B_ * K_ * C_;
        transpose_tmpl_kernel<<<(n + 255) / 256, 256>>>(tmpl);
    }
    {
        int n = C_ * NP_ * 9;
        pack_weights_kernel<<<(n + 255) / 256, 256>>>(w);
    }
    {
        dim3 g(YT_, B_, CT_);
        conv_om_kernel<<<g, 384>>>(sr);
    }
    {
        int n = B_ * OC_ * OHW_;
        reduce_om_kernel<<<(n + 255) / 256, 256>>>(bias);
    }
    {
        deform_xcorr_kernel<<<1250, 256>>>(out);
    }
}

// round 7
// speedup vs baseline: 1.6993x; 1.1052x over previous
#include <cuda_runtime.h>
#include <cstdint>
#include <math.h>

// Problem constants
constexpr int B_  = 8;
constexpr int C_  = 256;
constexpr int H_  = 31;
constexpr int W_  = 31;
constexpr int T_  = 7;
constexpr int K_  = 49;      // T*T
constexpr int OC_ = 147;     // 3*K
constexpr int NP_ = 74;      // oc pairs (padded 148)
constexpr int OH_ = 25;
constexpr int OW_ = 25;
constexpr int HW_ = H_ * W_; // 961
constexpr int OHW_= OH_ * OW_; // 625
constexpr int CT_ = 4;       // C split tiles
constexpr int CPT_= C_ / CT_;// 64 channels per tile
constexpr int YT_ = 9;       // y tiles of 3 rows (27 >= 25)

// Scratch (device globals; no allocations allowed)
__device__ float g_srT[B_ * HW_ * C_];                 // (B,H,W,C)
__device__ float g_tmplT[B_ * K_ * C_];                // (B,K,C)
__device__ float g_om[B_ * OC_ * OHW_];                // reduced conv out
__device__ float g_part[CT_ * B_ * OC_ * OHW_];        // conv partials
__device__ float2 g_wpk[C_ * NP_ * 9];                 // packed weights [c][pair][tap]

// packed f32x2 helpers
#define FMA_F32X2(d, a, b, c) \
    asm("fma.rn.f32x2 %0, %1, %2, %3;" : "=l"(d) : "l"(a), "l"(b), "l"(c))
#define PACK_DUP(d, v) \
    asm("mov.b64 %0, {%1, %1};" : "=l"(d) : "f"(v))
#define UNPACK2(lo, hi, p) \
    asm("mov.b64 {%0, %1}, %2;" : "=f"(lo), "=f"(hi) : "l"(p))

// ---------------------------------------------------------------------------
// transpose sr (B,C,HW) -> (B,HW,C)
// ---------------------------------------------------------------------------
__global__ void transpose_sr_kernel(const float* __restrict__ sr) {
    __shared__ float tile[32][33];
    int b  = blockIdx.z;
    int p0 = blockIdx.x * 32;
    int c0 = blockIdx.y * 32;
    int tx = threadIdx.x, ty = threadIdx.y;
    #pragma unroll
    for (int yy = 0; yy < 32; yy += 8) {
        int c = c0 + ty + yy, p = p0 + tx;
        if (p < HW_) tile[ty + yy][tx] = sr[(b * C_ + c) * HW_ + p];
    }
    __syncthreads();
    #pragma unroll
    for (int yy = 0; yy < 32; yy += 8) {
        int p = p0 + ty + yy, c = c0 + tx;
        if (p < HW_) g_srT[(b * HW_ + p) * C_ + c] = tile[tx][ty + yy];
    }
}

// transpose tmpl (B,C,K) -> (B,K,C)
__global__ void transpose_tmpl_kernel(const float* __restrict__ tmpl) {
    int t = blockIdx.x * 256 + threadIdx.x;
    if (t < B_ * K_ * C_) {
        int c = t % C_;
        int k = (t / C_) % K_;
        int b = t / (C_ * K_);
        g_tmplT[t] = tmpl[(b * C_ + c) * K_ + k];
    }
}

// pack conv weights: (147,256,3,3) -> g_wpk[c][pair][tap] float2 (oc even/odd)
__global__ void pack_weights_kernel(const float* __restrict__ w) {
    int t = blockIdx.x * 256 + threadIdx.x;
    if (t < C_ * NP_ * 9) {
        int tap = t % 9;
        int p   = (t / 9) % NP_;
        int c   = t / (9 * NP_);
        int o0 = 2 * p, o1 = 2 * p + 1;
        float v0 = w[o0 * (C_ * 9) + c * 9 + tap];
        float v1 = (o1 < OC_) ? w[o1 * (C_ * 9) + c * 9 + tap] : 0.0f;
        g_wpk[t] = make_float2(v0, v1);
    }
}

// ---------------------------------------------------------------------------
// K2: 3x3 conv on cropped region, f32x2 packed math, split-C partials.
// grid = (YT_=9, B_=8, CT_=4) = 288 blocks <= 296 capacity -> SINGLE wave.
// block = 384 threads; og=tid/5 (74 oc-pairs), xg=tid%5 (5 x each),
// 3 output rows per block.
// sr slice (64 ch x 5 rows) staged into smem ONCE (one barrier total);
// weights read directly via LDG (L1/L2-cached, warp-broadcast) — no smem.
// ---------------------------------------------------------------------------
__global__ void __launch_bounds__(384, 2) conv_om_kernel(
    const float* __restrict__ sr)
{
    __shared__ float s_sr[CPT_][5][33];   // 42.2 KB

    const int by = blockIdx.x;
    const int b  = blockIdx.y;
    const int ct = blockIdx.z;
    const int tid = threadIdx.x;

    const int og = tid / 5;          // 0..76
    const int xg = tid % 5;
    const bool active = (og < NP_);  // 370 active
    const int x_base = xg * 5;
    const int y_base = by * 3;
    const int cbase  = ct * CPT_;

    // stage entire sr slice: 64 ch x rows y_base-1..y_base+3 x padded cols
    for (int e = tid; e < CPT_ * 5 * 33; e += 384) {
        int cc  = e / 165;
        int rem = e % 165;
        int r   = rem / 33;
        int xp  = rem % 33;
        int gy  = y_base + r - 1;
        int gx  = xp - 1;
        float v = 0.f;
        if (gy >= 0 && gy < H_ && gx >= 0 && gx < W_)
            v = sr[((b * C_ + cbase + cc) * H_ + gy) * W_ + gx];
        s_sr[cc][r][xp] = v;
    }
    __syncthreads();

    unsigned long long acc[3][5];    // [yy][xx]
    #pragma unroll
    for (int yy = 0; yy < 3; yy++)
        #pragma unroll
        for (int xx = 0; xx < 5; xx++) acc[yy][xx] = 0ull;

    if (active) {
        const unsigned long long* __restrict__ wp0 =
            (const unsigned long long*)g_wpk + (size_t)og * 9;
        #pragma unroll 2
        for (int c = 0; c < CPT_; c++) {
            // this thread's 9 packed taps for channel (cbase+c)
            unsigned long long wq[9];
            const unsigned long long* wp = wp0 + (size_t)(cbase + c) * (NP_ * 9);
            #pragma unroll
            for (int t = 0; t < 9; t++) wq[t] = __ldg(wp + t);

            #pragma unroll
            for (int ir = 0; ir < 5; ir++) {
                #pragma unroll
                for (int u = 0; u < 7; u++) {
                    unsigned long long rp;
                    {
                        float v = s_sr[c][ir][x_base + u];
                        PACK_DUP(rp, v);
                    }
                    #pragma unroll
                    for (int dx = 0; dx < 3; dx++) {
                        const int xx = u - dx;
                        if (xx >= 0 && xx < 5) {
                            #pragma unroll
                            for (int dy = 0; dy < 3; dy++) {
                                const int yy = ir - dy;
                                if (yy >= 0 && yy < 3)
                                    FMA_F32X2(acc[yy][xx], rp,
                                              wq[dy * 3 + dx], acc[yy][xx]);
                            }
                        }
                    }
                }
            }
        }

        int o_even = og * 2;
        #pragma unroll
        for (int yy = 0; yy < 3; yy++) {
            int y = y_base + yy;
            if (y >= OH_) continue;
            #pragma unroll
            for (int xx = 0; xx < 5; xx++) {
                float lo, hi;
                UNPACK2(lo, hi, acc[yy][xx]);
                int base = ct * (B_ * OC_ * OHW_) +
                           (b * OC_ + o_even) * OHW_ + y * OW_ + x_base + xx;
                g_part[base] = lo;
                if (o_even + 1 < OC_) g_part[base + OHW_] = hi;
            }
        }
    }
}

// sum partials + bias -> g_om
__global__ void reduce_om_kernel(const float* __restrict__ bias) {
    int t = blockIdx.x * 256 + threadIdx.x;
    if (t < B_ * OC_ * OHW_) {
        int oc = (t / OHW_) % OC_;
        float s = bias[oc];
        #pragma unroll
        for (int ct = 0; ct < CT_; ct++)
            s += g_part[ct * (B_ * OC_ * OHW_) + t];
        g_om[t] = s;
    }
}

// ---------------------------------------------------------------------------
// K3: deformable bilinear gather + weighted correlation (vectorized).
// grid = 1250 blocks, block = 256 = 4 groups x 64 threads (float4 channels).
// ---------------------------------------------------------------------------
__global__ void __launch_bounds__(256) deform_xcorr_kernel(float* __restrict__ out)
{
    __shared__ int4   sA4[4][K_];
    __shared__ float4 sW4[4][K_];

    const int tid = threadIdx.x;

    if (tid < 4 * K_) {
        const int g2 = tid / K_;
        const int k  = tid % K_;
        const int p  = blockIdx.x * 4 + g2;
        const int b  = p / OHW_;
        const int rem = p % OHW_;
        const int i  = rem / OW_;
        const int j  = rem % OW_;

        const int base = (b * OC_ + k) * OHW_ + i * OW_ + j;
        float oy = g_om[base];
        float ox = g_om[base + 49 * OHW_];
        float mz = g_om[base + 98 * OHW_];
        float m  = 1.0f / (1.0f + __expf(-mz));

        float ys = (float)i + (float)(k / T_) + oy;
        float xs = (float)j + (float)(k % T_) + ox;
        float y0f = floorf(ys), x0f = floorf(xs);
        float wy = ys - y0f, wx = xs - x0f;
        float y1f = y0f + 1.0f, x1f = x0f + 1.0f;

        bool vy0 = (y0f >= 0.0f) && (y0f <= (float)(H_ - 1));
        bool vy1 = (y1f >= 0.0f) && (y1f <= (float)(H_ - 1));
        bool vx0 = (x0f >= 0.0f) && (x0f <= (float)(W_ - 1));
        bool vx1 = (x1f >= 0.0f) && (x1f <= (float)(W_ - 1));

        float w00 = (1.0f - wy) * (1.0f - wx) * m; if (!(vy0 && vx0)) w00 = 0.0f;
        float w01 = (1.0f - wy) * wx          * m; if (!(vy0 && vx1)) w01 = 0.0f;
        float w10 = wy          * (1.0f - wx) * m; if (!(vy1 && vx0)) w10 = 0.0f;
        float w11 = wy          * wx          * m; if (!(vy1 && vx1)) w11 = 0.0f;

        int y0 = (int)fminf(fmaxf(y0f, 0.0f), (float)(H_ - 1));
        int y1 = (int)fminf(fmaxf(y1f, 0.0f), (float)(H_ - 1));
        int x0 = (int)fminf(fmaxf(x0f, 0.0f), (float)(W_ - 1));
        int x1 = (int)fminf(fmaxf(x1f, 0.0f), (float)(W_ - 1));

        sA4[g2][k] = make_int4((y0 * W_ + x0) * (C_ * 4),
                               (y0 * W_ + x1) * (C_ * 4),
                               (y1 * W_ + x0) * (C_ * 4),
                               (y1 * W_ + x1) * (C_ * 4));
        sW4[g2][k] = make_float4(w00, w01, w10, w11);
    }
    __syncthreads();

    const int g  = tid / 64;
    const int c4 = tid % 64;
    const int p  = blockIdx.x * 4 + g;
    const int b  = p / OHW_;
    const int rem = p % OHW_;
    const int i  = rem / OW_;
    const int j  = rem % OW_;

    const char* srTb = (const char*)(g_srT + (size_t)b * HW_ * C_) + c4 * 16;
    const float4* tT = (const float4*)(g_tmplT + (size_t)b * K_ * C_) + c4;

    float4 acc = make_float4(0.f, 0.f, 0.f, 0.f);
    #pragma unroll 7
    for (int k = 0; k < K_; k++) {
        int4   a  = sA4[g][k];
        float4 wv = sW4[g][k];
        float4 v00 = *(const float4*)(srTb + a.x);
        float4 v01 = *(const float4*)(srTb + a.y);
        float4 v10 = *(const float4*)(srTb + a.z);
        float4 v11 = *(const float4*)(srTb + a.w);
        float4 tv  = tT[(size_t)k * 64];

        float sx, sy, sz, sw;
        sx = wv.x * v00.x; sx = fmaf(wv.y, v01.x, sx); sx = fmaf(wv.z, v10.x, sx); sx = fmaf(wv.w, v11.x, sx);
        sy = wv.x * v00.y; sy = fmaf(wv.y, v01.y, sy); sy = fmaf(wv.z, v10.y, sy); sy = fmaf(wv.w, v11.y, sy);
        sz = wv.x * v00.z; sz = fmaf(wv.y, v01.z, sz); sz = fmaf(wv.z, v10.z, sz); sz = fmaf(wv.w, v11.z, sz);
        sw = wv.x * v00.w; sw = fmaf(wv.y, v01.w, sw); sw = fmaf(wv.z, v10.w, sw); sw = fmaf(wv.w, v11.w, sw);

        acc.x = fmaf(tv.x, sx, acc.x);
        acc.y = fmaf(tv.y, sy, acc.y);
        acc.z = fmaf(tv.z, sz, acc.z);
        acc.w = fmaf(tv.w, sw, acc.w);
    }

    const int c = c4 * 4;
    float* op = out + ((size_t)(b * C_ + c) * OH_ + i) * OW_ + j;
    op[0]        = acc.x;
    op[OHW_]     = acc.y;
    op[2 * OHW_] = acc.z;
    op[3 * OHW_] = acc.w;
}

// ---------------------------------------------------------------------------
extern "C" void kernel_launch(void* const* d_in, const int* in_sizes, int n_in,
                              void* d_out, int out_size)
{
    const float* sr   = (const float*)d_in[0];
    const float* tmpl = (const float*)d_in[1];
    const float* w    = (const float*)d_in[2];
    const float* bias = (const float*)d_in[3];
    float* out = (float*)d_out;

    {
        dim3 tb(32, 8);
        dim3 tg((HW_ + 31) / 32, C_ / 32, B_);
        transpose_sr_kernel<<<tg, tb>>>(sr);
    }
    {
        int n = B_ * K_ * C_;
        transpose_tmpl_kernel<<<(n + 255) / 256, 256>>>(tmpl);
    }
    {
        int n = C_ * NP_ * 9;
        pack_weights_kernel<<<(n + 255) / 256, 256>>>(w);
    }
    {
        dim3 g(YT_, B_, CT_);
        conv_om_kernel<<<g, 384>>>(sr);
    }
    {
        int n = B_ * OC_ * OHW_;
        reduce_om_kernel<<<(n + 255) / 256, 256>>>(bias);
    }
    {
        deform_xcorr_kernel<<<1250, 256>>>(out);
    }
}